// round 6
// baseline (speedup 1.0000x reference)
#include <cuda_runtime.h>
#include <cuda_bf16.h>
#include <cstdint>

// ---------------- scratch (device globals; no runtime allocs) ---------------
__device__ float d_xn [16777216];   // LN(x) tf32; later reused as g buffer
__device__ float d_xfn[  786432];   // LN(xf) tf32
__device__ float d_q  [16777216];   // q (tf32)
__device__ float d_k  [ 1048576];   // k (tf32)
__device__ float d_v  [ 1048576];   // v (tf32)
__device__ float d_kT [ 1048576];   // k transposed [bh][d][n] (tf32)
__device__ float d_S  [67108864];   // scores / probs [bh][t][n]
__device__ float d_y  [16777216];   // attention output
__device__ float d_eo [    8192];   // emb_out (scale|shift) fp32
__device__ float d_se [    4096];   // silu(emb)
__device__ float d_Wq [ 1048576];
__device__ float d_Wk [  786432];
__device__ float d_Wv [  786432];
__device__ float d_Wo [ 1048576];

// ---------------- helpers ----------------
__device__ __forceinline__ float tf32r(float x) {
    uint32_t u; asm volatile("cvt.rna.tf32.f32 %0, %1;" : "=r"(u) : "f"(x));
    return __uint_as_float(u);
}
__device__ __forceinline__ float silu_f(float x) { return x / (1.f + __expf(-x)); }
__device__ __forceinline__ void cp_async16(void* smem, const void* gmem) {
    uint32_t s = (uint32_t)__cvta_generic_to_shared(smem);
    asm volatile("cp.async.cg.shared.global [%0], [%1], 16;\n" :: "r"(s), "l"(gmem));
}
__device__ __forceinline__ void cp_commit() { asm volatile("cp.async.commit_group;\n" ::); }
template<int NN> __device__ __forceinline__ void cp_wait() {
    asm volatile("cp.async.wait_group %0;\n" :: "n"(NN));
}
__device__ __forceinline__ void mma_tf32(float* d, const float* a, const float* b) {
    const uint32_t* A = reinterpret_cast<const uint32_t*>(a);
    const uint32_t* B = reinterpret_cast<const uint32_t*>(b);
    asm volatile(
        "mma.sync.aligned.m16n8k8.row.col.f32.tf32.tf32.f32 "
        "{%0,%1,%2,%3}, {%4,%5,%6,%7}, {%8,%9}, {%0,%1,%2,%3};\n"
        : "+f"(d[0]), "+f"(d[1]), "+f"(d[2]), "+f"(d[3])
        : "r"(A[0]), "r"(A[1]), "r"(A[2]), "r"(A[3]), "r"(B[0]), "r"(B[1]));
}

// ---------------- generic batched-strided tf32 GEMM ----------------
// C = A@B (+bias)(+res), optional tf32-round of outputs.
// A row-major [M,K] lda; B row-major [K,N] ldb. Batch z: outer=z/nInner,
// inner=z%nInner. Requires M%BM==0, N%BN==0, K%16==0, BM==128.
template<int BM, int BN, int WM, int WN>
__global__ __launch_bounds__(256)
void gemm_tf32_kernel(const float* __restrict__ A, const float* __restrict__ B,
                      float* __restrict__ C, const float* __restrict__ bias,
                      const float* __restrict__ res,
                      int M, int N, int K, int lda, int ldb, int ldc,
                      long long sAo, long long sAi, long long sBo, long long sBi,
                      long long sCo, long long sCi, int nInner, int roundOut)
{
    constexpr int BK = 16;
    constexpr int WTM = BM / WM, WTN = BN / WN;
    constexpr int MI = WTM / 16, NI = WTN / 8;

    __shared__ float As[2][BM][BK + 4];   // row = 20 floats -> conflict-free frags
    __shared__ float Bs[2][BK][BN + 8];   // (BN+8)%32==8   -> conflict-free frags

    const int z = blockIdx.z;
    const int outer = z / nInner, inner = z - outer * nInner;
    A += outer * sAo + inner * sAi;
    B += outer * sBo + inner * sBi;
    C += outer * sCo + inner * sCi;
    if (res) res += outer * sCo + inner * sCi;

    const int tid = threadIdx.x;
    const int warp = tid >> 5, lane = tid & 31;
    const int wm = warp % WM, wn = warp / WM;
    const int gid = lane >> 2, tig = lane & 3;
    const int blockM = blockIdx.y * BM, blockN = blockIdx.x * BN;

    const int a_row = tid >> 2;
    const int a_col = (tid & 3) << 2;
    constexpr int B_COLS4 = BN / 4;
    constexpr int B_RPP = 256 / B_COLS4;
    constexpr int B_PASSES = BK / B_RPP;
    const int b_row = tid / B_COLS4;
    const int b_col = (tid % B_COLS4) << 2;

    const float* Ab = A + (long long)blockM * lda;
    const float* Bb = B + blockN;

    auto loadStage = [&](int kt, int s) {
        const float* Ag = Ab + kt * BK;
        #pragma unroll
        for (int p = 0; p < 2; p++) {
            int r = a_row + p * 64;
            cp_async16(&As[s][r][a_col], Ag + (long long)r * lda + a_col);
        }
        const float* Bg = Bb + (long long)(kt * BK) * ldb;
        #pragma unroll
        for (int p = 0; p < B_PASSES; p++) {
            int r = b_row + p * B_RPP;
            cp_async16(&Bs[s][r][b_col], Bg + (long long)r * ldb + b_col);
        }
        cp_commit();
    };

    float acc[MI][NI][4];
    #pragma unroll
    for (int mi = 0; mi < MI; mi++)
        #pragma unroll
        for (int ni = 0; ni < NI; ni++)
            #pragma unroll
            for (int r = 0; r < 4; r++) acc[mi][ni][r] = 0.f;

    const int KT = K / BK;
    const int wrow = wm * WTM, wcol = wn * WTN;

    loadStage(0, 0);
    for (int kt = 0; kt < KT; kt++) {
        const int s = kt & 1;
        if (kt + 1 < KT) { loadStage(kt + 1, s ^ 1); cp_wait<1>(); }
        else             { cp_wait<0>(); }
        __syncthreads();

        #pragma unroll
        for (int ks = 0; ks < 2; ks++) {
            float af[MI][4], bf[NI][2];
            #pragma unroll
            for (int mi = 0; mi < MI; mi++) {
                const int r0 = wrow + mi * 16 + gid, c0 = ks * 8 + tig;
                af[mi][0] = As[s][r0    ][c0    ];
                af[mi][1] = As[s][r0 + 8][c0    ];
                af[mi][2] = As[s][r0    ][c0 + 4];
                af[mi][3] = As[s][r0 + 8][c0 + 4];
            }
            #pragma unroll
            for (int ni = 0; ni < NI; ni++) {
                const int c0 = wcol + ni * 8 + gid, r0 = ks * 8 + tig;
                bf[ni][0] = Bs[s][r0    ][c0];
                bf[ni][1] = Bs[s][r0 + 4][c0];
            }
            #pragma unroll
            for (int mi = 0; mi < MI; mi++)
                #pragma unroll
                for (int ni = 0; ni < NI; ni++)
                    mma_tf32(acc[mi][ni], af[mi], bf[ni]);
        }
        __syncthreads();
    }

    #pragma unroll
    for (int mi = 0; mi < MI; mi++)
        #pragma unroll
        for (int ni = 0; ni < NI; ni++) {
            const int gr0 = blockM + wrow + mi * 16 + gid;
            const int gc  = blockN + wcol + ni * 8 + tig * 2;
            float bx = 0.f, by = 0.f;
            if (bias) { bx = bias[gc]; by = bias[gc + 1]; }
            #pragma unroll
            for (int half = 0; half < 2; half++) {
                const int gr = gr0 + half * 8;
                float v0 = acc[mi][ni][half * 2 + 0] + bx;
                float v1 = acc[mi][ni][half * 2 + 1] + by;
                const long long off = (long long)gr * ldc + gc;
                if (res) { v0 += res[off]; v1 += res[off + 1]; }
                if (roundOut) { v0 = tf32r(v0); v1 = tf32r(v1); }
                float2 o; o.x = v0; o.y = v1;
                *reinterpret_cast<float2*>(C + off) = o;
            }
        }
}

// ---------------- LayerNorm (1 block / row) ----------------
__global__ void ln_kernel(const float* __restrict__ X, float* __restrict__ Y,
                          const float* __restrict__ gam, const float* __restrict__ bet,
                          int Dlen, int roundOut)
{
    const int row = blockIdx.x;
    const float4* x4 = reinterpret_cast<const float4*>(X + (long long)row * Dlen);
    float4* y4 = reinterpret_cast<float4*>(Y + (long long)row * Dlen);
    const int nv = Dlen >> 2;
    const int tid = threadIdx.x, lane = tid & 31, warp = tid >> 5;

    float s = 0.f, ss = 0.f;
    for (int i = tid; i < nv; i += 256) {
        float4 v = x4[i];
        s  += v.x + v.y + v.z + v.w;
        ss += v.x*v.x + v.y*v.y + v.z*v.z + v.w*v.w;
    }
    #pragma unroll
    for (int o = 16; o > 0; o >>= 1) {
        s  += __shfl_xor_sync(0xffffffffu, s, o);
        ss += __shfl_xor_sync(0xffffffffu, ss, o);
    }
    __shared__ float rs[8], rss[8], stat[2];
    if (lane == 0) { rs[warp] = s; rss[warp] = ss; }
    __syncthreads();
    if (tid == 0) {
        float ts = 0.f, tss = 0.f;
        #pragma unroll
        for (int w = 0; w < 8; w++) { ts += rs[w]; tss += rss[w]; }
        const float mu = ts / (float)Dlen;
        const float var = tss / (float)Dlen - mu * mu;
        stat[0] = mu; stat[1] = rsqrtf(var + 1e-5f);
    }
    __syncthreads();
    const float mu = stat[0], rstd = stat[1];
    const float4* g4 = reinterpret_cast<const float4*>(gam);
    const float4* b4 = reinterpret_cast<const float4*>(bet);
    for (int i = tid; i < nv; i += 256) {
        float4 v = x4[i], g = g4[i], b = b4[i];
        v.x = (v.x - mu) * rstd * g.x + b.x;
        v.y = (v.y - mu) * rstd * g.y + b.y;
        v.z = (v.z - mu) * rstd * g.z + b.z;
        v.w = (v.w - mu) * rstd * g.w + b.w;
        if (roundOut) { v.x=tf32r(v.x); v.y=tf32r(v.y); v.z=tf32r(v.z); v.w=tf32r(v.w); }
        y4[i] = v;
    }
}

// ---------------- AdaLN modulate + SiLU (row=1024, T=4096) ----------------
__global__ void modulate_kernel(const float* __restrict__ Yin, const float* __restrict__ eo,
                                const float* __restrict__ gam, const float* __restrict__ bet,
                                float* __restrict__ Out)
{
    const int row = blockIdx.x, b = row >> 12;
    const float4* x4 = reinterpret_cast<const float4*>(Yin + (long long)row * 1024);
    float4* o4 = reinterpret_cast<float4*>(Out + (long long)row * 1024);
    const int tid = threadIdx.x, lane = tid & 31, warp = tid >> 5;

    float4 v = x4[tid];
    float s  = v.x + v.y + v.z + v.w;
    float ss = v.x*v.x + v.y*v.y + v.z*v.z + v.w*v.w;
    #pragma unroll
    for (int o = 16; o > 0; o >>= 1) {
        s  += __shfl_xor_sync(0xffffffffu, s, o);
        ss += __shfl_xor_sync(0xffffffffu, ss, o);
    }
    __shared__ float rs[8], rss[8], stat[2];
    if (lane == 0) { rs[warp] = s; rss[warp] = ss; }
    __syncthreads();
    if (tid == 0) {
        float ts = 0.f, tss = 0.f;
        #pragma unroll
        for (int w = 0; w < 8; w++) { ts += rs[w]; tss += rss[w]; }
        const float mu = ts * (1.f / 1024.f);
        const float var = tss * (1.f / 1024.f) - mu * mu;
        stat[0] = mu; stat[1] = rsqrtf(var + 1e-5f);
    }
    __syncthreads();
    const float mu = stat[0], rstd = stat[1];
    const float4 g  = reinterpret_cast<const float4*>(gam)[tid];
    const float4 bb = reinterpret_cast<const float4*>(bet)[tid];
    const float4 sc = reinterpret_cast<const float4*>(eo + b * 2048)[tid];
    const float4 sh = reinterpret_cast<const float4*>(eo + b * 2048 + 1024)[tid];
    float4 o; float h;
    h = ((v.x-mu)*rstd*g.x + bb.x) * (1.f+sc.x) + sh.x; o.x = tf32r(silu_f(h));
    h = ((v.y-mu)*rstd*g.y + bb.y) * (1.f+sc.y) + sh.y; o.y = tf32r(silu_f(h));
    h = ((v.z-mu)*rstd*g.z + bb.z) * (1.f+sc.z) + sh.z; o.z = tf32r(silu_f(h));
    h = ((v.w-mu)*rstd*g.w + bb.w) * (1.f+sc.w) + sh.w; o.w = tf32r(silu_f(h));
    o4[tid] = o;
}

// ---------------- softmax over rows of 256 (0.125 folded), tf32 out --------
__global__ void softmax_kernel(float* __restrict__ S)
{
    const int lane = threadIdx.x & 31, warp = threadIdx.x >> 5;
    const long long row = (long long)blockIdx.x * 8 + warp;
    float4* p = reinterpret_cast<float4*>(S + row * 256);
    float4 v0 = p[lane], v1 = p[lane + 32];
    const float sc = 0.125f;
    v0.x*=sc; v0.y*=sc; v0.z*=sc; v0.w*=sc;
    v1.x*=sc; v1.y*=sc; v1.z*=sc; v1.w*=sc;
    float m = fmaxf(fmaxf(fmaxf(v0.x,v0.y),fmaxf(v0.z,v0.w)),
                    fmaxf(fmaxf(v1.x,v1.y),fmaxf(v1.z,v1.w)));
    #pragma unroll
    for (int o = 16; o > 0; o >>= 1) m = fmaxf(m, __shfl_xor_sync(0xffffffffu, m, o));
    v0.x=__expf(v0.x-m); v0.y=__expf(v0.y-m); v0.z=__expf(v0.z-m); v0.w=__expf(v0.w-m);
    v1.x=__expf(v1.x-m); v1.y=__expf(v1.y-m); v1.z=__expf(v1.z-m); v1.w=__expf(v1.w-m);
    float sum = v0.x+v0.y+v0.z+v0.w+v1.x+v1.y+v1.z+v1.w;
    #pragma unroll
    for (int o = 16; o > 0; o >>= 1) sum += __shfl_xor_sync(0xffffffffu, sum, o);
    const float inv = 1.f / sum;
    v0.x=tf32r(v0.x*inv); v0.y=tf32r(v0.y*inv); v0.z=tf32r(v0.z*inv); v0.w=tf32r(v0.w*inv);
    v1.x=tf32r(v1.x*inv); v1.y=tf32r(v1.y*inv); v1.z=tf32r(v1.z*inv); v1.w=tf32r(v1.w*inv);
    p[lane] = v0; p[lane + 32] = v1;
}

// ---------------- small utility kernels ----------------
__global__ void tf32copy_kernel(const float* __restrict__ s, float* __restrict__ d, int n) {
    int i = blockIdx.x * 256 + threadIdx.x;
    if (i < n) d[i] = tf32r(s[i]);
}
__global__ void silu_emb_kernel(const float* __restrict__ e, float* __restrict__ se) {
    int i = blockIdx.x * 256 + threadIdx.x;
    if (i < 4096) se[i] = silu_f(e[i]);
}
// eo[b][j] = silu(emb[b])·We[:,j] + be[j]   (We row-major [1024,2048])
__global__ void embgemm_kernel(const float* __restrict__ se, const float* __restrict__ We,
                               const float* __restrict__ be, float* __restrict__ eo)
{
    const int b = blockIdx.y;
    const int j = blockIdx.x * 256 + threadIdx.x;
    const float* s = se + b * 1024;
    float acc = 0.f;
    #pragma unroll 4
    for (int k = 0; k < 1024; k++) acc += s[k] * We[k * 2048 + j];
    eo[b * 2048 + j] = acc + be[j];
}
// kT[bh][d][n] = k[(b*256+n)*1024 + h*64 + d]
__global__ void transpose_k_kernel(const float* __restrict__ k, float* __restrict__ kT)
{
    const int n = threadIdx.x;          // 0..255
    const int d = blockIdx.x;           // 0..63
    const int bh = blockIdx.y;          // 0..63
    const int b = bh >> 4, h = bh & 15;
    kT[(long long)bh * 16384 + d * 256 + n] =
        k[((long long)(b * 256 + n)) * 1024 + h * 64 + d];
}

// ---------------- host ----------------
static float* symf(const void* s) { void* p = nullptr; cudaGetSymbolAddress(&p, s); return (float*)p; }

extern "C" void kernel_launch(void* const* d_in, const int* in_sizes, int n_in,
                              void* d_out, int out_size)
{
    const float* x       = (const float*)d_in[0];
    const float* xf      = (const float*)d_in[1];
    const float* emb     = (const float*)d_in[2];
    const float* norm_g  = (const float*)d_in[3];
    const float* norm_b  = (const float*)d_in[4];
    const float* tnorm_g = (const float*)d_in[5];
    const float* tnorm_b = (const float*)d_in[6];
    const float* Wq      = (const float*)d_in[7];
    const float* bq      = (const float*)d_in[8];
    const float* Wk      = (const float*)d_in[9];
    const float* bk      = (const float*)d_in[10];
    const float* Wv      = (const float*)d_in[11];
    const float* bv      = (const float*)d_in[12];
    const float* We      = (const float*)d_in[13];
    const float* be      = (const float*)d_in[14];
    const float* snorm_g = (const float*)d_in[15];
    const float* snorm_b = (const float*)d_in[16];
    const float* Wo      = (const float*)d_in[17];
    const float* bo      = (const float*)d_in[18];
    float* out = (float*)d_out;

    float* xn  = symf(d_xn);  float* xfn = symf(d_xfn);
    float* q   = symf(d_q);   float* kbuf= symf(d_k);
    float* vbuf= symf(d_v);   float* kT  = symf(d_kT);
    float* S   = symf(d_S);   float* y   = symf(d_y);
    float* eo  = symf(d_eo);  float* se  = symf(d_se);
    float* wq  = symf(d_Wq);  float* wk  = symf(d_Wk);
    float* wv  = symf(d_Wv);  float* wo  = symf(d_Wo);

    // prep
    ln_kernel<<<16384, 256>>>(x,  xn,  norm_g,  norm_b,  1024, 1);
    ln_kernel<<<1024,  256>>>(xf, xfn, tnorm_g, tnorm_b, 768,  1);
    tf32copy_kernel<<<4096, 256>>>(Wq, wq, 1048576);
    tf32copy_kernel<<<3072, 256>>>(Wk, wk, 786432);
    tf32copy_kernel<<<3072, 256>>>(Wv, wv, 786432);
    tf32copy_kernel<<<4096, 256>>>(Wo, wo, 1048576);
    silu_emb_kernel<<<16, 256>>>(emb, se);
    embgemm_kernel<<<dim3(8, 4), 256>>>(se, We, be, eo);

    // q = LN(x)@Wq + bq   [16384,1024]x[1024,1024]
    gemm_tf32_kernel<128,128,4,2><<<dim3(8, 128, 1), 256>>>(
        xn, wq, q, bq, nullptr, 16384, 1024, 1024, 1024, 1024, 1024,
        0, 0, 0, 0, 0, 0, 1, 1);
    // k,v = LN(xf)@Wk/Wv + b   [1024,768]x[768,1024]
    gemm_tf32_kernel<128,128,4,2><<<dim3(8, 8, 1), 256>>>(
        xfn, wk, kbuf, bk, nullptr, 1024, 1024, 768, 768, 1024, 1024,
        0, 0, 0, 0, 0, 0, 1, 1);
    gemm_tf32_kernel<128,128,4,2><<<dim3(8, 8, 1), 256>>>(
        xfn, wv, vbuf, bv, nullptr, 1024, 1024, 768, 768, 1024, 1024,
        0, 0, 0, 0, 0, 0, 1, 1);
    transpose_k_kernel<<<dim3(64, 64), 256>>>(kbuf, kT);

    // S[bh] = q[b,:,h,:] @ kT[bh]   M=4096 N=256 K=64, 64 batches
    gemm_tf32_kernel<128,128,4,2><<<dim3(2, 32, 64), 256>>>(
        q, kT, S, nullptr, nullptr, 4096, 256, 64, 1024, 256, 256,
        4194304LL, 64LL, 262144LL, 16384LL, 16777216LL, 1048576LL, 16, 0);

    softmax_kernel<<<32768, 256>>>(S);

    // y[b,:,h,:] = P[bh] @ v[b,:,h,:]   M=4096 N=64 K=256
    gemm_tf32_kernel<128,64,4,2><<<dim3(1, 32, 64), 256>>>(
        S, vbuf, y, nullptr, nullptr, 4096, 64, 256, 256, 1024, 1024,
        16777216LL, 1048576LL, 262144LL, 64LL, 4194304LL, 64LL, 16, 0);

    // g = tf32(silu(LN(y)*(1+scale)+shift))  (reuse xn)
    modulate_kernel<<<16384, 256>>>(y, eo, snorm_g, snorm_b, xn);

    // out = x + g@Wo + bo
    gemm_tf32_kernel<128,128,4,2><<<dim3(8, 128, 1), 256>>>(
        xn, wo, out, bo, x, 16384, 1024, 1024, 1024, 1024, 1024,
        0, 0, 0, 0, 0, 0, 1, 0);
}

// round 7
// speedup vs baseline: 1.0796x; 1.0796x over previous
#include <cuda_runtime.h>
#include <cuda_bf16.h>
#include <cstdint>

// ---------------- scratch (device globals; no runtime allocs) ---------------
__device__ float d_xn [16777216];   // LN(x) tf32; later reused as g buffer
__device__ float d_xfn[  786432];   // LN(xf) tf32
__device__ float d_q  [16777216];   // q (tf32)
__device__ float d_k  [ 1048576];   // k (tf32)
__device__ float d_v  [ 1048576];   // v (tf32)
__device__ float d_y  [16777216];   // attention output
__device__ float d_eo [    8192];   // emb_out (scale|shift) fp32
__device__ float d_se [    4096];   // silu(emb)
__device__ float d_Wq [ 1048576];
__device__ float d_Wk [  786432];
__device__ float d_Wv [  786432];
__device__ float d_Wo [ 1048576];

// ---------------- helpers ----------------
__device__ __forceinline__ float tf32r(float x) {
    uint32_t u; asm volatile("cvt.rna.tf32.f32 %0, %1;" : "=r"(u) : "f"(x));
    return __uint_as_float(u);
}
__device__ __forceinline__ float silu_f(float x) { return x / (1.f + __expf(-x)); }
__device__ __forceinline__ void cp_async16(void* smem, const void* gmem) {
    uint32_t s = (uint32_t)__cvta_generic_to_shared(smem);
    asm volatile("cp.async.cg.shared.global [%0], [%1], 16;\n" :: "r"(s), "l"(gmem));
}
__device__ __forceinline__ void cp_commit() { asm volatile("cp.async.commit_group;\n" ::); }
template<int NN> __device__ __forceinline__ void cp_wait() {
    asm volatile("cp.async.wait_group %0;\n" :: "n"(NN));
}
__device__ __forceinline__ void mma_tf32(float* d, const float* a, const float* b) {
    const uint32_t* A = reinterpret_cast<const uint32_t*>(a);
    const uint32_t* B = reinterpret_cast<const uint32_t*>(b);
    asm volatile(
        "mma.sync.aligned.m16n8k8.row.col.f32.tf32.tf32.f32 "
        "{%0,%1,%2,%3}, {%4,%5,%6,%7}, {%8,%9}, {%0,%1,%2,%3};\n"
        : "+f"(d[0]), "+f"(d[1]), "+f"(d[2]), "+f"(d[3])
        : "r"(A[0]), "r"(A[1]), "r"(A[2]), "r"(A[3]), "r"(B[0]), "r"(B[1]));
}

// ---------------- generic batched-strided tf32 GEMM ----------------
template<int BM, int BN, int WM, int WN>
__global__ __launch_bounds__(256)
void gemm_tf32_kernel(const float* __restrict__ A, const float* __restrict__ B,
                      float* __restrict__ C, const float* __restrict__ bias,
                      const float* __restrict__ res,
                      int M, int N, int K, int lda, int ldb, int ldc,
                      long long sAo, long long sAi, long long sBo, long long sBi,
                      long long sCo, long long sCi, int nInner, int roundOut)
{
    constexpr int BK = 16;
    constexpr int WTM = BM / WM, WTN = BN / WN;
    constexpr int MI = WTM / 16, NI = WTN / 8;

    __shared__ float As[2][BM][BK + 4];
    __shared__ float Bs[2][BK][BN + 8];

    const int z = blockIdx.z;
    const int outer = z / nInner, inner = z - outer * nInner;
    A += outer * sAo + inner * sAi;
    B += outer * sBo + inner * sBi;
    C += outer * sCo + inner * sCi;
    if (res) res += outer * sCo + inner * sCi;

    const int tid = threadIdx.x;
    const int warp = tid >> 5, lane = tid & 31;
    const int wm = warp % WM, wn = warp / WM;
    const int gid = lane >> 2, tig = lane & 3;
    const int blockM = blockIdx.y * BM, blockN = blockIdx.x * BN;

    const int a_row = tid >> 2;
    const int a_col = (tid & 3) << 2;
    constexpr int B_COLS4 = BN / 4;
    constexpr int B_RPP = 256 / B_COLS4;
    constexpr int B_PASSES = BK / B_RPP;
    const int b_row = tid / B_COLS4;
    const int b_col = (tid % B_COLS4) << 2;

    const float* Ab = A + (long long)blockM * lda;
    const float* Bb = B + blockN;

    auto loadStage = [&](int kt, int s) {
        const float* Ag = Ab + kt * BK;
        #pragma unroll
        for (int p = 0; p < 2; p++) {
            int r = a_row + p * 64;
            cp_async16(&As[s][r][a_col], Ag + (long long)r * lda + a_col);
        }
        const float* Bg = Bb + (long long)(kt * BK) * ldb;
        #pragma unroll
        for (int p = 0; p < B_PASSES; p++) {
            int r = b_row + p * B_RPP;
            cp_async16(&Bs[s][r][b_col], Bg + (long long)r * ldb + b_col);
        }
        cp_commit();
    };

    float acc[MI][NI][4];
    #pragma unroll
    for (int mi = 0; mi < MI; mi++)
        #pragma unroll
        for (int ni = 0; ni < NI; ni++)
            #pragma unroll
            for (int r = 0; r < 4; r++) acc[mi][ni][r] = 0.f;

    const int KT = K / BK;
    const int wrow = wm * WTM, wcol = wn * WTN;

    loadStage(0, 0);
    for (int kt = 0; kt < KT; kt++) {
        const int s = kt & 1;
        if (kt + 1 < KT) { loadStage(kt + 1, s ^ 1); cp_wait<1>(); }
        else             { cp_wait<0>(); }
        __syncthreads();

        #pragma unroll
        for (int ks = 0; ks < 2; ks++) {
            float af[MI][4], bf[NI][2];
            #pragma unroll
            for (int mi = 0; mi < MI; mi++) {
                const int r0 = wrow + mi * 16 + gid, c0 = ks * 8 + tig;
                af[mi][0] = As[s][r0    ][c0    ];
                af[mi][1] = As[s][r0 + 8][c0    ];
                af[mi][2] = As[s][r0    ][c0 + 4];
                af[mi][3] = As[s][r0 + 8][c0 + 4];
            }
            #pragma unroll
            for (int ni = 0; ni < NI; ni++) {
                const int c0 = wcol + ni * 8 + gid, r0 = ks * 8 + tig;
                bf[ni][0] = Bs[s][r0    ][c0];
                bf[ni][1] = Bs[s][r0 + 4][c0];
            }
            #pragma unroll
            for (int mi = 0; mi < MI; mi++)
                #pragma unroll
                for (int ni = 0; ni < NI; ni++)
                    mma_tf32(acc[mi][ni], af[mi], bf[ni]);
        }
        __syncthreads();
    }

    #pragma unroll
    for (int mi = 0; mi < MI; mi++)
        #pragma unroll
        for (int ni = 0; ni < NI; ni++) {
            const int gr0 = blockM + wrow + mi * 16 + gid;
            const int gc  = blockN + wcol + ni * 8 + tig * 2;
            float bx = 0.f, by = 0.f;
            if (bias) { bx = bias[gc]; by = bias[gc + 1]; }
            #pragma unroll
            for (int half = 0; half < 2; half++) {
                const int gr = gr0 + half * 8;
                float v0 = acc[mi][ni][half * 2 + 0] + bx;
                float v1 = acc[mi][ni][half * 2 + 1] + by;
                const long long off = (long long)gr * ldc + gc;
                if (res) { v0 += res[off]; v1 += res[off + 1]; }
                if (roundOut) { v0 = tf32r(v0); v1 = tf32r(v1); }
                float2 o; o.x = v0; o.y = v1;
                *reinterpret_cast<float2*>(C + off) = o;
            }
        }
}

// ---------------- fused flash cross-attention ----------------
// One CTA: 128 q-rows of one (b,h). N=256 keys in 2 blocks of 128.
// Warp layout WM=8 (each warp owns 16 full rows) -> softmax reductions are
// intra-quad shfl only. P re-fragmented via smem (tf32-rounded).
__global__ __launch_bounds__(256)
void flash_kernel(const float* __restrict__ q, const float* __restrict__ k,
                  const float* __restrict__ v, float* __restrict__ y)
{
    extern __shared__ float sm[];
    float* Qs = sm;                    // [128][68]
    float* Ks = Qs + 128 * 68;         // [128][68]
    float* Vs = Ks + 128 * 68;         // [128][68]
    float* Ps = Vs + 128 * 68;         // [128][132]

    const int tb = blockIdx.x;         // 0..31
    const int bh = blockIdx.y;         // 0..63
    const int b = bh >> 4, h = bh & 15;
    const int tid = threadIdx.x, warp = tid >> 5, lane = tid & 31;
    const int gid = lane >> 2, tig = lane & 3;
    const int wrow = warp * 16;

    const float* qg = q + ((long long)(b * 4096 + tb * 128)) * 1024 + h * 64;
    const float* kg = k + ((long long)(b * 256)) * 1024 + h * 64;
    const float* vg = v + ((long long)(b * 256)) * 1024 + h * 64;

    const int lr = tid >> 4;            // 0..15
    const int lc = (tid & 15) << 2;     // 0..60

    #pragma unroll
    for (int p = 0; p < 8; p++)
        cp_async16(&Qs[(lr + p * 16) * 68 + lc], qg + (long long)(lr + p * 16) * 1024 + lc);
    #pragma unroll
    for (int p = 0; p < 8; p++)
        cp_async16(&Ks[(lr + p * 16) * 68 + lc], kg + (long long)(lr + p * 16) * 1024 + lc);
    #pragma unroll
    for (int p = 0; p < 8; p++)
        cp_async16(&Vs[(lr + p * 16) * 68 + lc], vg + (long long)(lr + p * 16) * 1024 + lc);
    cp_commit();

    float oacc[8][4];
    #pragma unroll
    for (int i = 0; i < 8; i++) { oacc[i][0] = oacc[i][1] = oacc[i][2] = oacc[i][3] = 0.f; }
    float m0 = -1e30f, m1 = -1e30f, l0 = 0.f, l1 = 0.f;

    #pragma unroll
    for (int kb = 0; kb < 2; kb++) {
        cp_wait<0>();
        __syncthreads();

        // S = Q @ K^T (128x128, this warp: rows [wrow, wrow+16))
        float sacc[16][4];
        #pragma unroll
        for (int i = 0; i < 16; i++) { sacc[i][0] = sacc[i][1] = sacc[i][2] = sacc[i][3] = 0.f; }
        #pragma unroll
        for (int ks = 0; ks < 8; ks++) {
            float a[4];
            a[0] = Qs[(wrow + gid    ) * 68 + ks * 8 + tig    ];
            a[1] = Qs[(wrow + gid + 8) * 68 + ks * 8 + tig    ];
            a[2] = Qs[(wrow + gid    ) * 68 + ks * 8 + tig + 4];
            a[3] = Qs[(wrow + gid + 8) * 68 + ks * 8 + tig + 4];
            #pragma unroll
            for (int ni = 0; ni < 16; ni++) {
                float bb[2];
                bb[0] = Ks[(ni * 8 + gid) * 68 + ks * 8 + tig    ];
                bb[1] = Ks[(ni * 8 + gid) * 68 + ks * 8 + tig + 4];
                mma_tf32(sacc[ni], a, bb);
            }
        }

        // online softmax (rows r0 = wrow+gid, r1 = wrow+gid+8)
        float rm0 = -1e30f, rm1 = -1e30f;
        #pragma unroll
        for (int ni = 0; ni < 16; ni++) {
            sacc[ni][0] *= 0.125f; sacc[ni][1] *= 0.125f;
            sacc[ni][2] *= 0.125f; sacc[ni][3] *= 0.125f;
            rm0 = fmaxf(rm0, fmaxf(sacc[ni][0], sacc[ni][1]));
            rm1 = fmaxf(rm1, fmaxf(sacc[ni][2], sacc[ni][3]));
        }
        rm0 = fmaxf(rm0, __shfl_xor_sync(0xffffffffu, rm0, 1));
        rm0 = fmaxf(rm0, __shfl_xor_sync(0xffffffffu, rm0, 2));
        rm1 = fmaxf(rm1, __shfl_xor_sync(0xffffffffu, rm1, 1));
        rm1 = fmaxf(rm1, __shfl_xor_sync(0xffffffffu, rm1, 2));
        const float mn0 = fmaxf(m0, rm0), mn1 = fmaxf(m1, rm1);
        const float al0 = __expf(m0 - mn0), al1 = __expf(m1 - mn1);
        float ps0 = 0.f, ps1 = 0.f;
        #pragma unroll
        for (int ni = 0; ni < 16; ni++) {
            float p00 = __expf(sacc[ni][0] - mn0);
            float p01 = __expf(sacc[ni][1] - mn0);
            float p10 = __expf(sacc[ni][2] - mn1);
            float p11 = __expf(sacc[ni][3] - mn1);
            ps0 += p00 + p01; ps1 += p10 + p11;
            float2 w0; w0.x = tf32r(p00); w0.y = tf32r(p01);
            float2 w1; w1.x = tf32r(p10); w1.y = tf32r(p11);
            *reinterpret_cast<float2*>(&Ps[(wrow + gid    ) * 132 + ni * 8 + tig * 2]) = w0;
            *reinterpret_cast<float2*>(&Ps[(wrow + gid + 8) * 132 + ni * 8 + tig * 2]) = w1;
        }
        ps0 += __shfl_xor_sync(0xffffffffu, ps0, 1);
        ps0 += __shfl_xor_sync(0xffffffffu, ps0, 2);
        ps1 += __shfl_xor_sync(0xffffffffu, ps1, 1);
        ps1 += __shfl_xor_sync(0xffffffffu, ps1, 2);
        l0 = l0 * al0 + ps0;  l1 = l1 * al1 + ps1;
        m0 = mn0;  m1 = mn1;
        #pragma unroll
        for (int i = 0; i < 8; i++) {
            oacc[i][0] *= al0; oacc[i][1] *= al0;
            oacc[i][2] *= al1; oacc[i][3] *= al1;
        }
        __syncthreads();   // Ps published; Ks free

        if (kb == 0) {     // prefetch next K behind the PV mma
            #pragma unroll
            for (int p = 0; p < 8; p++)
                cp_async16(&Ks[(lr + p * 16) * 68 + lc],
                           kg + (long long)(128 + lr + p * 16) * 1024 + lc);
            cp_commit();
        }

        // O += P @ V (K-dim 128)
        #pragma unroll
        for (int ks = 0; ks < 16; ks++) {
            float a[4];
            a[0] = Ps[(wrow + gid    ) * 132 + ks * 8 + tig    ];
            a[1] = Ps[(wrow + gid + 8) * 132 + ks * 8 + tig    ];
            a[2] = Ps[(wrow + gid    ) * 132 + ks * 8 + tig + 4];
            a[3] = Ps[(wrow + gid + 8) * 132 + ks * 8 + tig + 4];
            #pragma unroll
            for (int ni = 0; ni < 8; ni++) {
                float bb[2];
                bb[0] = Vs[(ks * 8 + tig    ) * 68 + ni * 8 + gid];
                bb[1] = Vs[(ks * 8 + tig + 4) * 68 + ni * 8 + gid];
                mma_tf32(oacc[ni], a, bb);
            }
        }
        __syncthreads();   // Vs free

        if (kb == 0) {
            #pragma unroll
            for (int p = 0; p < 8; p++)
                cp_async16(&Vs[(lr + p * 16) * 68 + lc],
                           vg + (long long)(128 + lr + p * 16) * 1024 + lc);
            cp_commit();
        }
    }

    const float inv0 = 1.f / l0, inv1 = 1.f / l1;
    float* yg = y + ((long long)(b * 4096 + tb * 128 + wrow)) * 1024 + h * 64;
    #pragma unroll
    for (int ni = 0; ni < 8; ni++) {
        float2 w0; w0.x = oacc[ni][0] * inv0; w0.y = oacc[ni][1] * inv0;
        float2 w1; w1.x = oacc[ni][2] * inv1; w1.y = oacc[ni][3] * inv1;
        *reinterpret_cast<float2*>(&yg[(long long)gid * 1024 + ni * 8 + tig * 2]) = w0;
        *reinterpret_cast<float2*>(&yg[(long long)(gid + 8) * 1024 + ni * 8 + tig * 2]) = w1;
    }
}

// ---------------- LayerNorm (1 block / row) ----------------
__global__ void ln_kernel(const float* __restrict__ X, float* __restrict__ Y,
                          const float* __restrict__ gam, const float* __restrict__ bet,
                          int Dlen, int roundOut)
{
    const int row = blockIdx.x;
    const float4* x4 = reinterpret_cast<const float4*>(X + (long long)row * Dlen);
    float4* y4 = reinterpret_cast<float4*>(Y + (long long)row * Dlen);
    const int nv = Dlen >> 2;
    const int tid = threadIdx.x, lane = tid & 31, warp = tid >> 5;

    float s = 0.f, ss = 0.f;
    for (int i = tid; i < nv; i += 256) {
        float4 v = x4[i];
        s  += v.x + v.y + v.z + v.w;
        ss += v.x*v.x + v.y*v.y + v.z*v.z + v.w*v.w;
    }
    #pragma unroll
    for (int o = 16; o > 0; o >>= 1) {
        s  += __shfl_xor_sync(0xffffffffu, s, o);
        ss += __shfl_xor_sync(0xffffffffu, ss, o);
    }
    __shared__ float rs[8], rss[8], stat[2];
    if (lane == 0) { rs[warp] = s; rss[warp] = ss; }
    __syncthreads();
    if (tid == 0) {
        float ts = 0.f, tss = 0.f;
        #pragma unroll
        for (int w = 0; w < 8; w++) { ts += rs[w]; tss += rss[w]; }
        const float mu = ts / (float)Dlen;
        const float var = tss / (float)Dlen - mu * mu;
        stat[0] = mu; stat[1] = rsqrtf(var + 1e-5f);
    }
    __syncthreads();
    const float mu = stat[0], rstd = stat[1];
    const float4* g4 = reinterpret_cast<const float4*>(gam);
    const float4* b4 = reinterpret_cast<const float4*>(bet);
    for (int i = tid; i < nv; i += 256) {
        float4 v = x4[i], g = g4[i], b = b4[i];
        v.x = (v.x - mu) * rstd * g.x + b.x;
        v.y = (v.y - mu) * rstd * g.y + b.y;
        v.z = (v.z - mu) * rstd * g.z + b.z;
        v.w = (v.w - mu) * rstd * g.w + b.w;
        if (roundOut) { v.x=tf32r(v.x); v.y=tf32r(v.y); v.z=tf32r(v.z); v.w=tf32r(v.w); }
        y4[i] = v;
    }
}

// ---------------- AdaLN modulate + SiLU (row=1024, T=4096) ----------------
__global__ void modulate_kernel(const float* __restrict__ Yin, const float* __restrict__ eo,
                                const float* __restrict__ gam, const float* __restrict__ bet,
                                float* __restrict__ Out)
{
    const int row = blockIdx.x, b = row >> 12;
    const float4* x4 = reinterpret_cast<const float4*>(Yin + (long long)row * 1024);
    float4* o4 = reinterpret_cast<float4*>(Out + (long long)row * 1024);
    const int tid = threadIdx.x, lane = tid & 31, warp = tid >> 5;

    float4 v = x4[tid];
    float s  = v.x + v.y + v.z + v.w;
    float ss = v.x*v.x + v.y*v.y + v.z*v.z + v.w*v.w;
    #pragma unroll
    for (int o = 16; o > 0; o >>= 1) {
        s  += __shfl_xor_sync(0xffffffffu, s, o);
        ss += __shfl_xor_sync(0xffffffffu, ss, o);
    }
    __shared__ float rs[8], rss[8], stat[2];
    if (lane == 0) { rs[warp] = s; rss[warp] = ss; }
    __syncthreads();
    if (tid == 0) {
        float ts = 0.f, tss = 0.f;
        #pragma unroll
        for (int w = 0; w < 8; w++) { ts += rs[w]; tss += rss[w]; }
        const float mu = ts * (1.f / 1024.f);
        const float var = tss * (1.f / 1024.f) - mu * mu;
        stat[0] = mu; stat[1] = rsqrtf(var + 1e-5f);
    }
    __syncthreads();
    const float mu = stat[0], rstd = stat[1];
    const float4 g  = reinterpret_cast<const float4*>(gam)[tid];
    const float4 bb = reinterpret_cast<const float4*>(bet)[tid];
    const float4 sc = reinterpret_cast<const float4*>(eo + b * 2048)[tid];
    const float4 sh = reinterpret_cast<const float4*>(eo + b * 2048 + 1024)[tid];
    float4 o; float h;
    h = ((v.x-mu)*rstd*g.x + bb.x) * (1.f+sc.x) + sh.x; o.x = tf32r(silu_f(h));
    h = ((v.y-mu)*rstd*g.y + bb.y) * (1.f+sc.y) + sh.y; o.y = tf32r(silu_f(h));
    h = ((v.z-mu)*rstd*g.z + bb.z) * (1.f+sc.z) + sh.z; o.z = tf32r(silu_f(h));
    h = ((v.w-mu)*rstd*g.w + bb.w) * (1.f+sc.w) + sh.w; o.w = tf32r(silu_f(h));
    o4[tid] = o;
}

// ---------------- small utility kernels ----------------
__global__ void tf32copy_kernel(const float* __restrict__ s, float* __restrict__ d, int n) {
    int i = blockIdx.x * 256 + threadIdx.x;
    if (i < n) d[i] = tf32r(s[i]);
}
__global__ void silu_emb_kernel(const float* __restrict__ e, float* __restrict__ se) {
    int i = blockIdx.x * 256 + threadIdx.x;
    if (i < 4096) se[i] = silu_f(e[i]);
}
__global__ void embgemm_kernel(const float* __restrict__ se, const float* __restrict__ We,
                               const float* __restrict__ be, float* __restrict__ eo)
{
    const int b = blockIdx.y;
    const int j = blockIdx.x * 256 + threadIdx.x;
    const float* s = se + b * 1024;
    float acc = 0.f;
    #pragma unroll 4
    for (int kk = 0; kk < 1024; kk++) acc += s[kk] * We[kk * 2048 + j];
    eo[b * 2048 + j] = acc + be[j];
}

// ---------------- host ----------------
static float* symf(const void* s) { void* p = nullptr; cudaGetSymbolAddress(&p, s); return (float*)p; }

extern "C" void kernel_launch(void* const* d_in, const int* in_sizes, int n_in,
                              void* d_out, int out_size)
{
    const float* x       = (const float*)d_in[0];
    const float* xf      = (const float*)d_in[1];
    const float* emb     = (const float*)d_in[2];
    const float* norm_g  = (const float*)d_in[3];
    const float* norm_b  = (const float*)d_in[4];
    const float* tnorm_g = (const float*)d_in[5];
    const float* tnorm_b = (const float*)d_in[6];
    const float* Wq      = (const float*)d_in[7];
    const float* bq      = (const float*)d_in[8];
    const float* Wk      = (const float*)d_in[9];
    const float* bk      = (const float*)d_in[10];
    const float* Wv      = (const float*)d_in[11];
    const float* bv      = (const float*)d_in[12];
    const float* We      = (const float*)d_in[13];
    const float* be      = (const float*)d_in[14];
    const float* snorm_g = (const float*)d_in[15];
    const float* snorm_b = (const float*)d_in[16];
    const float* Wo      = (const float*)d_in[17];
    const float* bo      = (const float*)d_in[18];
    float* out = (float*)d_out;

    float* xn  = symf(d_xn);  float* xfn = symf(d_xfn);
    float* q   = symf(d_q);   float* kbuf= symf(d_k);
    float* vbuf= symf(d_v);   float* y   = symf(d_y);
    float* eo  = symf(d_eo);  float* se  = symf(d_se);
    float* wq  = symf(d_Wq);  float* wk  = symf(d_Wk);
    float* wv  = symf(d_Wv);  float* wo  = symf(d_Wo);

    const int FLASH_SMEM = (128 * 68 * 3 + 128 * 132) * 4;   // 172032 B
    cudaFuncSetAttribute(flash_kernel, cudaFuncAttributeMaxDynamicSharedMemorySize, FLASH_SMEM);

    // prep
    ln_kernel<<<16384, 256>>>(x,  xn,  norm_g,  norm_b,  1024, 1);
    ln_kernel<<<1024,  256>>>(xf, xfn, tnorm_g, tnorm_b, 768,  1);
    tf32copy_kernel<<<4096, 256>>>(Wq, wq, 1048576);
    tf32copy_kernel<<<3072, 256>>>(Wk, wk, 786432);
    tf32copy_kernel<<<3072, 256>>>(Wv, wv, 786432);
    tf32copy_kernel<<<4096, 256>>>(Wo, wo, 1048576);
    silu_emb_kernel<<<16, 256>>>(emb, se);
    embgemm_kernel<<<dim3(8, 4), 256>>>(se, We, be, eo);

    // q = LN(x)@Wq + bq
    gemm_tf32_kernel<128,128,4,2><<<dim3(8, 128, 1), 256>>>(
        xn, wq, q, bq, nullptr, 16384, 1024, 1024, 1024, 1024, 1024,
        0, 0, 0, 0, 0, 0, 1, 1);
    // k,v = LN(xf)@Wk/Wv + b
    gemm_tf32_kernel<128,128,4,2><<<dim3(8, 8, 1), 256>>>(
        xfn, wk, kbuf, bk, nullptr, 1024, 1024, 768, 768, 1024, 1024,
        0, 0, 0, 0, 0, 0, 1, 1);
    gemm_tf32_kernel<128,128,4,2><<<dim3(8, 8, 1), 256>>>(
        xfn, wv, vbuf, bv, nullptr, 1024, 1024, 768, 768, 1024, 1024,
        0, 0, 0, 0, 0, 0, 1, 1);

    // fused attention: y = softmax(q k^T / 8) v
    flash_kernel<<<dim3(32, 64), 256, FLASH_SMEM>>>(q, kbuf, vbuf, y);

    // g = tf32(silu(LN(y)*(1+scale)+shift))  (reuse xn)
    modulate_kernel<<<16384, 256>>>(y, eo, snorm_g, snorm_b, xn);

    // out = x + g@Wo + bo
    gemm_tf32_kernel<128,128,4,2><<<dim3(8, 128, 1), 256>>>(
        xn, wo, out, bo, x, 16384, 1024, 1024, 1024, 1024, 1024,
        0, 0, 0, 0, 0, 0, 1, 0);
}